// round 5
// baseline (speedup 1.0000x reference)
#include <cuda_runtime.h>
#include <cuda_fp16.h>
#include <cstdint>

#define M_DIM 16384
#define N_DIM 2048
#define K_DIM 2048

#define BM 128
#define BN 128
#define BK 64
#define LDSK 80   // 64 data + 16 pad: stride is 5*16B -> ldmatrix rows conflict-free

// Allocation-free device scratch (module-scope, permitted by _HX_ENFORCE rules).
__device__ __align__(256) int8_t g_x8[(size_t)M_DIM * K_DIM];     // 32 MB packed x
__device__ __align__(256) int8_t g_wT[(size_t)N_DIM * K_DIM];     // 4 MB weight^T [N][K]
__device__ int g_x_wide;
__device__ int g_w_wide;
__device__ const int8_t* g_xptr;

// ---------------------------------------------------------------------------
// Detect whether int inputs were widened to int32 by the harness.
// int32 values in [-127,127) always have high byte 0x00/0xFF; random int8
// bytes at those positions fail this test almost surely.
// ---------------------------------------------------------------------------
__global__ void detect_kernel(const uint8_t* __restrict__ x,
                              const uint8_t* __restrict__ w) {
    __shared__ int sx, sw;
    if (threadIdx.x == 0) { sx = 1; sw = 1; }
    __syncthreads();
    int okx = 1, okw = 1;
    for (int i = threadIdx.x; i < 1024; i += 256) {
        uint8_t bx = x[4 * i + 3];
        uint8_t bw = w[4 * i + 3];
        if (bx != 0x00 && bx != 0xFF) okx = 0;
        if (bw != 0x00 && bw != 0xFF) okw = 0;
    }
    if (!okx) atomicAnd(&sx, 0);
    if (!okw) atomicAnd(&sw, 0);
    __syncthreads();
    if (threadIdx.x == 0) {
        g_x_wide = sx;
        g_w_wide = sw;
        g_xptr = sx ? (const int8_t*)g_x8 : (const int8_t*)x;
    }
}

// ---------------------------------------------------------------------------
// Pack x int32 -> int8 (no-op when input is already int8).
// 16 values per thread, vectorized loads/stores.
// ---------------------------------------------------------------------------
__global__ void pack_x_kernel(const int4* __restrict__ x32) {
    if (!g_x_wide) return;
    const size_t e0 = ((size_t)blockIdx.x * blockDim.x + threadIdx.x) * 16;
    if (e0 >= (size_t)M_DIM * K_DIM) return;
    int8_t tmp[16];
#pragma unroll
    for (int j = 0; j < 4; j++) {
        int4 v = x32[e0 / 4 + j];
        tmp[4 * j + 0] = (int8_t)v.x;
        tmp[4 * j + 1] = (int8_t)v.y;
        tmp[4 * j + 2] = (int8_t)v.z;
        tmp[4 * j + 3] = (int8_t)v.w;
    }
    *(int4*)&g_x8[e0] = *(const int4*)tmp;
}

// ---------------------------------------------------------------------------
// Transpose weight [K][N] -> g_wT [N][K], dtype-adaptive read.
// ---------------------------------------------------------------------------
__global__ void transpose_w_kernel(const void* __restrict__ w) {
    __shared__ int8_t tile[32][33];
    const int n0 = blockIdx.x * 32;
    const int k0 = blockIdx.y * 32;
    const int tx = threadIdx.x;   // 0..31
    const int ty = threadIdx.y;   // 0..7
    const int wide = g_w_wide;
    const int8_t* w8 = (const int8_t*)w;
    const int*    w32 = (const int*)w;
    if (wide) {
#pragma unroll
        for (int j = 0; j < 32; j += 8)
            tile[ty + j][tx] = (int8_t)w32[(size_t)(k0 + ty + j) * N_DIM + (n0 + tx)];
    } else {
#pragma unroll
        for (int j = 0; j < 32; j += 8)
            tile[ty + j][tx] = w8[(size_t)(k0 + ty + j) * N_DIM + (n0 + tx)];
    }
    __syncthreads();
#pragma unroll
    for (int j = 0; j < 32; j += 8)
        g_wT[(size_t)(n0 + ty + j) * K_DIM + (k0 + tx)] = tile[tx][ty + j];
}

// ---------------------------------------------------------------------------
// helpers
// ---------------------------------------------------------------------------
__device__ __forceinline__ uint32_t cvta_smem(const void* p) {
    return (uint32_t)__cvta_generic_to_shared(p);
}

__device__ __forceinline__ void ldsm_x4(uint32_t& r0, uint32_t& r1,
                                        uint32_t& r2, uint32_t& r3, uint32_t addr) {
    asm volatile("ldmatrix.sync.aligned.m8n8.x4.shared.b16 {%0,%1,%2,%3}, [%4];\n"
                 : "=r"(r0), "=r"(r1), "=r"(r2), "=r"(r3) : "r"(addr));
}

#define MMA_S8(ACC, AF, B0, B1)                                              \
    asm volatile("mma.sync.aligned.m16n8k32.row.col.s32.s8.s8.s32 "          \
                 "{%0,%1,%2,%3}, {%4,%5,%6,%7}, {%8,%9}, {%0,%1,%2,%3};\n"   \
                 : "+r"(ACC[0]), "+r"(ACC[1]), "+r"(ACC[2]), "+r"(ACC[3])    \
                 : "r"(AF[0]), "r"(AF[1]), "r"(AF[2]), "r"(AF[3]),           \
                   "r"(B0), "r"(B1))

// ---------------------------------------------------------------------------
// Int8 GEMM: out = x @ weight + bias.  IMMA m16n8k32, ldmatrix fragments,
// cp.async double-buffered. CTA 128x128x64, 8 warps = 4(M)x2(N).
// ---------------------------------------------------------------------------
__global__ __launch_bounds__(256, 2)
void int8_gemm_kernel(const __half* __restrict__ bias,
                      float* __restrict__ out) {
    __shared__ __align__(16) int8_t smA[2][BM][LDSK];
    __shared__ __align__(16) int8_t smB[2][BN][LDSK];

    const int tid  = threadIdx.x;
    const int bn   = blockIdx.x;          // 0..15
    const int bm   = blockIdx.y;          // 0..127
    const int lane = tid & 31;
    const int wid  = tid >> 5;
    const int warp_m = wid & 3;
    const int warp_n = wid >> 2;

    const int lr   = lane & 7;
    const int tsel = lane >> 3;

    const int8_t* A  = g_xptr;            // detect kernel chose packed vs raw
    const int8_t* gA = A + (size_t)(bm * BM) * K_DIM;
    const int8_t* gB = g_wT + (size_t)(bn * BN) * K_DIM;

    int acc[2][8][4];
#pragma unroll
    for (int mt = 0; mt < 2; mt++)
#pragma unroll
        for (int nt = 0; nt < 8; nt++)
#pragma unroll
            for (int i = 0; i < 4; i++) acc[mt][nt][i] = 0;

    auto load_stage = [&](int st, int kb) {
        const int kbase = kb * BK;
#pragma unroll
        for (int i = 0; i < 2; i++) {
            const int c   = tid * 2 + i;        // 0..511
            const int row = c >> 2;
            const int col = (c & 3) * 16;
            uint32_t da = cvta_smem(&smA[st][row][col]);
            const int8_t* sa = gA + (size_t)row * K_DIM + kbase + col;
            asm volatile("cp.async.cg.shared.global [%0], [%1], 16;\n"
                         :: "r"(da), "l"(sa));
            uint32_t db = cvta_smem(&smB[st][row][col]);
            const int8_t* sb = gB + (size_t)row * K_DIM + kbase + col;
            asm volatile("cp.async.cg.shared.global [%0], [%1], 16;\n"
                         :: "r"(db), "l"(sb));
        }
        asm volatile("cp.async.commit_group;\n");
    };

    const int KB = K_DIM / BK;   // 32
    load_stage(0, 0);

    for (int kb = 0; kb < KB; kb++) {
        if (kb + 1 < KB) {
            load_stage((kb + 1) & 1, kb + 1);
            asm volatile("cp.async.wait_group 1;\n");
        } else {
            asm volatile("cp.async.wait_group 0;\n");
        }
        __syncthreads();

        const int st = kb & 1;
#pragma unroll
        for (int ks = 0; ks < BK; ks += 32) {
            const int ka = ks + ((tsel & 2) ? 16 : 0);
            uint32_t afr[2][4];
#pragma unroll
            for (int mt = 0; mt < 2; mt++) {
                const int ar = warp_m * 32 + mt * 16 + lr + ((tsel & 1) ? 8 : 0);
                ldsm_x4(afr[mt][0], afr[mt][1], afr[mt][2], afr[mt][3],
                        cvta_smem(&smA[st][ar][ka]));
            }
            const int kboff = ks + ((tsel & 1) ? 16 : 0);
#pragma unroll
            for (int nt = 0; nt < 8; nt += 2) {
                const int br = warp_n * 64 + (nt + ((tsel >> 1) & 1)) * 8 + lr;
                uint32_t b0, b1, b2, b3;
                ldsm_x4(b0, b1, b2, b3, cvta_smem(&smB[st][br][kboff]));
#pragma unroll
                for (int mt = 0; mt < 2; mt++) {
                    MMA_S8(acc[mt][nt],     afr[mt], b0, b1);
                    MMA_S8(acc[mt][nt + 1], afr[mt], b2, b3);
                }
            }
        }
        __syncthreads();
    }

    // epilogue: int32 -> f32 + bias (bias is zeros; half-read safe either way)
#pragma unroll
    for (int mt = 0; mt < 2; mt++) {
        const int m0 = bm * BM + warp_m * 32 + mt * 16 + (lane >> 2);
#pragma unroll
        for (int nt = 0; nt < 8; nt++) {
            const int n = bn * BN + warp_n * 64 + nt * 8 + 2 * (lane & 3);
            const __half2 bh = *(const __half2*)&bias[n];
            const float2 bf = __half22float2(bh);
            float2 v0, v1;
            v0.x = (float)acc[mt][nt][0] + bf.x;
            v0.y = (float)acc[mt][nt][1] + bf.y;
            v1.x = (float)acc[mt][nt][2] + bf.x;
            v1.y = (float)acc[mt][nt][3] + bf.y;
            *(float2*)&out[(size_t)m0 * N_DIM + n]       = v0;
            *(float2*)&out[(size_t)(m0 + 8) * N_DIM + n] = v1;
        }
    }
}

// ---------------------------------------------------------------------------
extern "C" void kernel_launch(void* const* d_in, const int* in_sizes, int n_in,
                              void* d_out, int out_size) {
    // Identify inputs purely by element count (robust to any ordering):
    // x = 16384*2048 = 33554432, weight = 2048*2048 = 4194304, bias = 2048.
    const void* x = nullptr;
    const void* w = nullptr;
    const void* b = nullptr;
    for (int i = 0; i < n_in; i++) {
        if (in_sizes[i] == M_DIM * K_DIM)      x = d_in[i];
        else if (in_sizes[i] == K_DIM * N_DIM) w = d_in[i];
        else                                   b = d_in[i];
    }
    float* out = (float*)d_out;

    detect_kernel<<<1, 256>>>((const uint8_t*)x, (const uint8_t*)w);
    pack_x_kernel<<<(M_DIM * (size_t)K_DIM) / (256 * 16), 256>>>((const int4*)x);
    transpose_w_kernel<<<dim3(N_DIM / 32, K_DIM / 32), dim3(32, 8)>>>(w);
    int8_gemm_kernel<<<dim3(N_DIM / BN, M_DIM / BM), 256>>>((const __half*)b, out);
}

// round 8
// speedup vs baseline: 4.2658x; 4.2658x over previous
#include <cuda_runtime.h>
#include <cuda_fp16.h>
#include <cuda_bf16.h>
#include <cstdint>

#define M_DIM 16384
#define N_DIM 2048
#define K_DIM 2048

// ---- tcgen05 availability: only on arch-specific/family sm_100+ passes ----
#if defined(__CUDA_ARCH__) && (defined(__CUDA_ARCH_FEAT_SM103_ALL) ||          \
    defined(__CUDA_ARCH_FEAT_SM100_ALL) ||                                     \
    (defined(__CUDA_ARCH_FAMILY_SPECIFIC__) && (__CUDA_ARCH_FAMILY_SPECIFIC__ >= 1000)))
#define HAVE_TC 1
#else
#define HAVE_TC 0
#endif

// ---- allocation-free device scratch ---------------------------------------
__device__ __align__(256) __nv_bfloat16 g_xbf[(size_t)M_DIM * K_DIM];   // 64 MB
__device__ __align__(256) __nv_bfloat16 g_wTbf[(size_t)N_DIM * K_DIM]; //  8 MB [N][K]
__device__ __align__(256) int8_t g_x8[(size_t)M_DIM * K_DIM];   // 32 MB (fallback)
__device__ __align__(256) int8_t g_wT[(size_t)N_DIM * K_DIM];   //  4 MB (fallback)
__device__ int g_x_wide;
__device__ int g_w_wide;
__device__ int g_have_tc;
__device__ const int8_t* g_xptr;

__global__ void probe_kernel() { g_have_tc = HAVE_TC; }

// ---------------------------------------------------------------------------
// Detect int32-widened inputs (high byte of each 4B group is 0x00/0xFF).
// ---------------------------------------------------------------------------
__global__ void detect_kernel(const uint8_t* __restrict__ x,
                              const uint8_t* __restrict__ w) {
    __shared__ int sx, sw;
    if (threadIdx.x == 0) { sx = 1; sw = 1; }
    __syncthreads();
    int okx = 1, okw = 1;
    for (int i = threadIdx.x; i < 1024; i += 256) {
        uint8_t bx = x[4 * i + 3];
        uint8_t bw = w[4 * i + 3];
        if (bx != 0x00 && bx != 0xFF) okx = 0;
        if (bw != 0x00 && bw != 0xFF) okw = 0;
    }
    if (!okx) atomicAnd(&sx, 0);
    if (!okw) atomicAnd(&sw, 0);
    __syncthreads();
    if (threadIdx.x == 0) {
        g_x_wide = sx;
        g_w_wide = sw;
        g_xptr = sx ? (const int8_t*)g_x8 : (const int8_t*)x;
    }
}

// ---------------------------------------------------------------------------
// x -> bf16 (tc path).  8 elements/thread.
// ---------------------------------------------------------------------------
__global__ void pack_x_bf16_kernel(const void* __restrict__ xin) {
    if (!g_have_tc) return;
    const size_t e0 = ((size_t)blockIdx.x * blockDim.x + threadIdx.x) * 8;
    if (e0 >= (size_t)M_DIM * K_DIM) return;
    __nv_bfloat16 tmp[8];
    if (g_x_wide) {
        const int4* p = (const int4*)xin + e0 / 4;
        int4 v0 = p[0], v1 = p[1];
        tmp[0] = __int2bfloat16_rn(v0.x); tmp[1] = __int2bfloat16_rn(v0.y);
        tmp[2] = __int2bfloat16_rn(v0.z); tmp[3] = __int2bfloat16_rn(v0.w);
        tmp[4] = __int2bfloat16_rn(v1.x); tmp[5] = __int2bfloat16_rn(v1.y);
        tmp[6] = __int2bfloat16_rn(v1.z); tmp[7] = __int2bfloat16_rn(v1.w);
    } else {
        const int8_t* p = (const int8_t*)xin + e0;
        int8_t b[8];
        *(int2*)b = *(const int2*)p;
#pragma unroll
        for (int j = 0; j < 8; j++) tmp[j] = __int2bfloat16_rn((int)b[j]);
    }
    *(uint4*)&g_xbf[e0] = *(const uint4*)tmp;
}

// ---------------------------------------------------------------------------
// weight [K][N] -> g_wTbf [N][K] bf16 (tc path).
// ---------------------------------------------------------------------------
__global__ void pack_w_bf16T_kernel(const void* __restrict__ w) {
    if (!g_have_tc) return;
    __shared__ __nv_bfloat16 tile[32][33];
    const int n0 = blockIdx.x * 32;
    const int k0 = blockIdx.y * 32;
    const int tx = threadIdx.x;
    const int ty = threadIdx.y;
    if (g_w_wide) {
        const int* w32 = (const int*)w;
#pragma unroll
        for (int j = 0; j < 32; j += 8)
            tile[ty + j][tx] = __int2bfloat16_rn(w32[(size_t)(k0 + ty + j) * N_DIM + (n0 + tx)]);
    } else {
        const int8_t* w8 = (const int8_t*)w;
#pragma unroll
        for (int j = 0; j < 32; j += 8)
            tile[ty + j][tx] = __int2bfloat16_rn((int)w8[(size_t)(k0 + ty + j) * N_DIM + (n0 + tx)]);
    }
    __syncthreads();
#pragma unroll
    for (int j = 0; j < 32; j += 8)
        g_wTbf[(size_t)(n0 + ty + j) * K_DIM + (k0 + tx)] = tile[tx][ty + j];
}

// ---------------------------------------------------------------------------
// Fallback-path preprocessing (int8), gated off when tc path is live.
// ---------------------------------------------------------------------------
__global__ void pack_x_kernel(const int4* __restrict__ x32) {
    if (g_have_tc || !g_x_wide) return;
    const size_t e0 = ((size_t)blockIdx.x * blockDim.x + threadIdx.x) * 16;
    if (e0 >= (size_t)M_DIM * K_DIM) return;
    int8_t tmp[16];
#pragma unroll
    for (int j = 0; j < 4; j++) {
        int4 v = x32[e0 / 4 + j];
        tmp[4 * j + 0] = (int8_t)v.x;
        tmp[4 * j + 1] = (int8_t)v.y;
        tmp[4 * j + 2] = (int8_t)v.z;
        tmp[4 * j + 3] = (int8_t)v.w;
    }
    *(int4*)&g_x8[e0] = *(const int4*)tmp;
}

__global__ void transpose_w_kernel(const void* __restrict__ w) {
    if (g_have_tc) return;
    __shared__ int8_t tile[32][33];
    const int n0 = blockIdx.x * 32;
    const int k0 = blockIdx.y * 32;
    const int tx = threadIdx.x;
    const int ty = threadIdx.y;
    if (g_w_wide) {
        const int* w32 = (const int*)w;
#pragma unroll
        for (int j = 0; j < 32; j += 8)
            tile[ty + j][tx] = (int8_t)w32[(size_t)(k0 + ty + j) * N_DIM + (n0 + tx)];
    } else {
        const int8_t* w8 = (const int8_t*)w;
#pragma unroll
        for (int j = 0; j < 32; j += 8)
            tile[ty + j][tx] = w8[(size_t)(k0 + ty + j) * N_DIM + (n0 + tx)];
    }
    __syncthreads();
#pragma unroll
    for (int j = 0; j < 32; j += 8)
        g_wT[(size_t)(n0 + ty + j) * K_DIM + (k0 + tx)] = tile[tx][ty + j];
}

// ---------------------------------------------------------------------------
__device__ __forceinline__ uint32_t cvta_smem(const void* p) {
    return (uint32_t)__cvta_generic_to_shared(p);
}

// ===========================================================================
// tcgen05 bf16 GEMM.  CTA tile 256x256, K-chunk 64 elements (128B rows, SW128).
// Two M=128 slabs x two N=128 atoms; TMEM D = 512 cols fp32.
// ===========================================================================
#define TBM 256
#define TBN 256
#define TBKE 64                          // bf16 elements per chunk
#define KCHUNKS (K_DIM / TBKE)           // 32

#define SWZ(o) ((o) ^ (((o) >> 3) & 0x70))

#define SM_TMEM 0
#define SM_MBAR 16
#define SM_A    1024                     // 2 stages x 32 KB
#define SM_B    (1024 + 2 * 32768)       // 2 stages x 32 KB
#define SMEM_TOTAL (1024 + 4 * 32768)    // 132096 B

#if HAVE_TC
__device__ __forceinline__ void mbar_init(uint32_t a, uint32_t cnt) {
    asm volatile("mbarrier.init.shared.b64 [%0], %1;" :: "r"(a), "r"(cnt) : "memory");
}
__device__ __forceinline__ void mbar_wait(uint32_t a, uint32_t parity) {
    asm volatile(
        "{\n\t"
        ".reg .pred P1;\n\t"
        "WAIT_LOOP_%=:\n\t"
        "mbarrier.try_wait.parity.shared.b64 P1, [%0], %1;\n\t"
        "@P1 bra.uni WAIT_DONE_%=;\n\t"
        "bra.uni WAIT_LOOP_%=;\n\t"
        "WAIT_DONE_%=:\n\t"
        "}"
        :: "r"(a), "r"(parity) : "memory");
}
// SW128 SMEM descriptor: layout=2, version=1 (Blackwell), SBO=64, LBO=1
static __device__ __forceinline__ uint64_t make_desc_sw128(uint32_t addr) {
    return ((uint64_t)2 << 61) | ((uint64_t)1 << 46) | ((uint64_t)64 << 32) |
           ((uint64_t)1 << 16) | (((uint64_t)addr >> 4) & 0x3FFF);
}
// idesc kind::f16 (bf16 in, fp32 acc): dtype F32@4, atype BF16@[7:9],
// btype BF16@[10:12], N/8@[17:22]=16 (N=128), M/16@[24:28]=8 (M=128)
#define IDESC_BF16 ((1u << 4) | (1u << 7) | (1u << 10) | (16u << 17) | (8u << 24))

__device__ __forceinline__ void mma_bf16_ss(uint32_t d_tmem, uint64_t a_desc,
                                            uint64_t b_desc, uint32_t en) {
    asm volatile(
        "{\n\t"
        ".reg .pred p;\n\t"
        "setp.ne.u32 p, %5, 0;\n\t"
        "tcgen05.mma.cta_group::1.kind::f16 [%0], %1, %2, %3, {%4,%4,%4,%4}, p;\n\t"
        "}"
        :: "r"(d_tmem), "l"(a_desc), "l"(b_desc), "r"(IDESC_BF16), "r"(0u), "r"(en)
        : "memory");
}
__device__ __forceinline__ void mma_commit(uint32_t mbar) {
    asm volatile(
        "tcgen05.commit.cta_group::1.mbarrier::arrive::one.shared::cluster.b64 [%0];"
        :: "r"(mbar) : "memory");
}
#endif  // HAVE_TC

__global__ __launch_bounds__(256, 1) __cluster_dims__(1, 1, 1)
void tc_gemm_kernel(const __half* __restrict__ bias, float* __restrict__ out) {
#if HAVE_TC
    extern __shared__ __align__(1024) char smem[];
    const uint32_t smem_base = cvta_smem(smem);
    const int tid  = threadIdx.x;
    const int lane = tid & 31;
    const int wid  = tid >> 5;
    const int bn   = blockIdx.x;     // 0..7
    const int bm   = blockIdx.y;     // 0..63

    const __nv_bfloat16* gA = g_xbf  + (size_t)(bm * TBM) * K_DIM;
    const __nv_bfloat16* gB = g_wTbf + (size_t)(bn * TBN) * K_DIM;

    if (wid == 0) {
        asm volatile("tcgen05.alloc.cta_group::1.sync.aligned.shared::cta.b32 [%0], %1;"
                     :: "r"(smem_base + SM_TMEM), "r"(512u) : "memory");
        asm volatile("tcgen05.relinquish_alloc_permit.cta_group::1.sync.aligned;");
    }
    if (tid == 0) {
        mbar_init(smem_base + SM_MBAR, 1);
        mbar_init(smem_base + SM_MBAR + 8, 1);
    }
    __syncthreads();

    uint32_t tmem;
    asm volatile("ld.shared.b32 %0, [%1];" : "=r"(tmem) : "r"(smem_base + SM_TMEM));

    // ---- chunk loader: A 32 KB + B 32 KB, 16B cp.async, SW128 -------------
    auto load_chunk = [&](int c) {
        const int st = c & 1;
        const int kk = c * TBKE;                 // element offset
        const uint32_t abase = smem_base + SM_A + st * 32768;
        const uint32_t bbase = smem_base + SM_B + st * 32768;
#pragma unroll
        for (int i = 0; i < 8; i++) {
            const int idx = tid + i * 256;       // 0..2047
            const int row = idx >> 3;            // 0..255
            const int ce  = (idx & 7) * 8;       // element col 0..56
            const uint32_t dst = abase + SWZ(row * 128 + ce * 2);
            const __nv_bfloat16* src = gA + (size_t)row * K_DIM + kk + ce;
            asm volatile("cp.async.cg.shared.global [%0], [%1], 16;\n"
                         :: "r"(dst), "l"(src));
        }
#pragma unroll
        for (int i = 0; i < 8; i++) {
            const int idx = tid + i * 256;
            const int row = idx >> 3;
            const int ce  = (idx & 7) * 8;
            const uint32_t dst = bbase + SWZ(row * 128 + ce * 2);
            const __nv_bfloat16* src = gB + (size_t)row * K_DIM + kk + ce;
            asm volatile("cp.async.cg.shared.global [%0], [%1], 16;\n"
                         :: "r"(dst), "l"(src));
        }
        asm volatile("cp.async.commit_group;\n");
    };

    load_chunk(0);
    load_chunk(1);

    int ph0 = 0, ph1 = 0;

    for (int c = 0; c < KCHUNKS; c++) {
        const int st = c & 1;
        if (c < KCHUNKS - 1) asm volatile("cp.async.wait_group 1;\n");
        else                 asm volatile("cp.async.wait_group 0;\n");
        asm volatile("fence.proxy.async.shared::cta;" ::: "memory");
        __syncthreads();

        if (tid == 0) {
            const uint64_t ad = make_desc_sw128(smem_base + SM_A + st * 32768);
            const uint64_t bd = make_desc_sw128(smem_base + SM_B + st * 32768);
#pragma unroll
            for (int k = 0; k < 4; k++) {        // k16 steps: +32B = +2 units
                const uint32_t en = (c > 0 || k > 0) ? 1u : 0u;
#pragma unroll
                for (int s = 0; s < 2; s++) {    // M slabs: +128 rows = +1024 units
                    const uint64_t a = ad + s * 1024 + k * 2;
                    mma_bf16_ss(tmem + s * 256,       a, bd + k * 2,        en);
                    mma_bf16_ss(tmem + s * 256 + 128, a, bd + 1024 + k * 2, en);
                }
            }
            mma_commit(smem_base + SM_MBAR + st * 8);
        }

        if (c + 2 < KCHUNKS) {
            if (st == 0) { mbar_wait(smem_base + SM_MBAR,     ph0); ph0 ^= 1; }
            else         { mbar_wait(smem_base + SM_MBAR + 8, ph1); ph1 ^= 1; }
            load_chunk(c + 2);
        }
    }

    mbar_wait(smem_base + SM_MBAR,     ph0);
    mbar_wait(smem_base + SM_MBAR + 8, ph1);
    asm volatile("tcgen05.fence::after_thread_sync;" ::: "memory");

    // ---- epilogue: warps 0-3 slab0 (cols 0..255), warps 4-7 slab1 ---------
    const int slab = wid >> 2;
    const int sp   = wid & 3;
    const size_t m = (size_t)(bm * TBM + slab * 128 + sp * 32 + lane);
    const uint32_t dbase = tmem + slab * 256;

#pragma unroll
    for (int cb = 0; cb < 256; cb += 32) {
        uint32_t r[32];
        asm volatile(
            "tcgen05.ld.sync.aligned.32x32b.x32.b32 "
            "{%0,%1,%2,%3,%4,%5,%6,%7,%8,%9,%10,%11,%12,%13,%14,%15,"
            "%16,%17,%18,%19,%20,%21,%22,%23,%24,%25,%26,%27,%28,%29,%30,%31}, [%32];"
            : "=r"(r[0]), "=r"(r[1]), "=r"(r[2]), "=r"(r[3]),
              "=r"(r[4]), "=r"(r[5]), "=r"(r[6]), "=r"(r[7]),
              "=r"(r[8]), "=r"(r[9]), "=r"(r[10]), "=r"(r[11]),
              "=r"(r[12]), "=r"(r[13]), "=r"(r[14]), "=r"(r[15]),
              "=r"(r[16]), "=r"(r[17]), "=r"(r[18]), "=r"(r[19]),
              "=r"(r[20]), "=r"(r[21]), "=r"(r[22]), "=r"(r[23]),
              "=r"(r[24]), "=r"(r[25]), "=r"(r[26]), "=r"(r[27]),
              "=r"(r[28]), "=r"(r[29]), "=r"(r[30]), "=r"(r[31])
            : "r"(dbase + cb));
        asm volatile("tcgen05.wait::ld.sync.aligned;" ::: "memory");

        const int n0 = bn * TBN + cb;
        float* op = out + m * N_DIM + n0;
#pragma unroll
        for (int j = 0; j < 32; j += 4) {
            float4 v;
            v.x = __uint_as_float(r[j + 0]) + __half2float(bias[n0 + j + 0]);
            v.y = __uint_as_float(r[j + 1]) + __half2float(bias[n0 + j + 1]);
            v.z = __uint_as_float(r[j + 2]) + __half2float(bias[n0 + j + 2]);
            v.w = __uint_as_float(r[j + 3]) + __half2float(bias[n0 + j + 3]);
            *(float4*)&op[j] = v;
        }
    }

    __syncthreads();
    if (wid == 0) {
        asm volatile("tcgen05.dealloc.cta_group::1.sync.aligned.b32 %0, %1;"
                     :: "r"(tmem), "r"(512u));
    }
#endif  // HAVE_TC
}

// ===========================================================================
// Fallback: proven R5 IMMA kernel (runs only when tcgen05 is unavailable).
// ===========================================================================
#define FBM 128
#define FBN 128
#define FBK 64
#define LDSK 80

__device__ __forceinline__ void ldsm_x4(uint32_t& r0, uint32_t& r1,
                                        uint32_t& r2, uint32_t& r3, uint32_t addr) {
    asm volatile("ldmatrix.sync.aligned.m8n8.x4.shared.b16 {%0,%1,%2,%3}, [%4];\n"
                 : "=r"(r0), "=r"(r1), "=r"(r2), "=r"(r3) : "r"(addr));
}

#define MMA_S8(ACC, AF, B0, B1)                                              \
    asm volatile("mma.sync.aligned.m16n8k32.row.col.s32.s8.s8.s32 "          \
                 "{%0,%1,%2,%3}, {%4,%5,%6,%7}, {%8,%9}, {%0,%1,%2,%3};\n"   \
                 : "+r"(ACC[0]), "+r"(ACC[1]), "+r"(ACC[2]), "+r"(ACC[3])    \
                 : "r"(AF[0]), "r"(AF[1]), "r"(AF[2]), "r"(AF[3]),           \
                   "r"(B0), "r"(B1))

__global__ __launch_bounds__(256, 2)
void imma_gemm_kernel(const __half* __restrict__ bias, float* __restrict__ out) {
    if (g_have_tc) return;

    __shared__ __align__(16) int8_t smA[2][FBM][LDSK];
    __shared__ __align__(16) int8_t smB[2][FBN][LDSK];

    const int tid  = threadIdx.x;
    const int bn   = blockIdx.x;
    const int bm   = blockIdx.y;
    const int lane = tid & 31;
    const int wid  = tid >> 5;
    const int warp_m = wid & 3;
    const int warp_n = wid >> 2;
    const int lr   = lane & 7;
    const int tsel = lane >> 3;

    const int8_t* A  = g_xptr;
    const int8_t* gA = A + (size_t)(bm * FBM) * K_DIM;
    const int8_t* gB = g_wT + (size_t)(bn * FBN) * K_DIM;

    int acc[2][8][4];
#pragma unroll
    for (int mt = 0; mt < 2; mt++)
#pragma unroll
        for (int nt = 0; nt < 8; nt++)
#pragma unroll
            for (int i = 0; i < 4; i++) acc[mt][nt][i] = 0;

    auto load_stage = [&](int st, int kb) {
        const int kbase = kb * FBK;
#pragma unroll
        for (int i = 0; i < 2; i++) {
            const int c   = tid * 2 + i;
            const int row = c >> 2;
            const int col = (c & 3) * 16;
            uint32_t da = cvta_smem(&smA[st][row][col]);
            const int8_t* sa = gA + (size_t)row * K_DIM + kbase + col;
            asm volatile("cp.async.cg.shared.global [%0], [%1], 16;\n"
                         :: "r"(da), "l"(sa));
            uint32_t db = cvta_smem(&smB[st][row][col]);
            const int8_t* sb = gB + (size_t)row * K_DIM + kbase + col;
            asm volatile("cp.async.cg.shared.global [%0], [%1], 16;\n"
                         :: "r"(db), "l"(sb));
        }
        asm volatile("cp.async.commit_group;\n");
    };

    const int KB = K_DIM / FBK;
    load_stage(0, 0);

    for (int kb = 0; kb < KB; kb++) {
        if (kb + 1 < KB) {
            load_stage((kb + 1) & 1, kb + 1);
            asm volatile("cp.async.wait_group 1;\n");
        } else {
            asm volatile("cp.async.wait_group 0;\n");
        }
        __syncthreads();

        const int st = kb & 1;
#pragma unroll
        for (int ks = 0; ks < FBK; ks += 32) {
            const int ka = ks + ((tsel & 2) ? 16 : 0);
            uint32_t afr[2][4];
#pragma unroll
            for (int mt = 0; mt < 2; mt++) {
                const int ar = warp_m * 32 + mt * 16 + lr + ((tsel & 1) ? 8 : 0);
                ldsm_x4(afr[mt][0], afr[mt][1], afr[mt][2], afr[mt][3],
                        cvta_smem(&smA[st][ar][ka]));
            }
            const int kboff = ks + ((tsel & 1) ? 16 : 0);
#pragma unroll
            for (int nt = 0; nt < 8; nt += 2) {
                const int br = warp_n * 64 + (nt + ((tsel >> 1) & 1)) * 8 + lr;
                uint32_t b0, b1, b2, b3;
                ldsm_x4(b0, b1, b2, b3, cvta_smem(&smB[st][br][kboff]));
#pragma unroll
                for (int mt = 0; mt < 2; mt++) {
                    MMA_S8(acc[mt][nt],     afr[mt], b0, b1);
                    MMA_S8(acc[mt][nt + 1], afr[mt], b2, b3);
                }
            }
        }
        __syncthreads();
    }

#pragma unroll
    for (int mt = 0; mt < 2; mt++) {
        const int m0 = bm * FBM + warp_m * 32 + mt * 16 + (lane >> 2);
#pragma unroll
        for (int nt = 0; nt < 8; nt++) {
            const int n = bn * FBN + warp_n * 64 + nt * 8 + 2 * (lane & 3);
            const __half2 bh = *(const __half2*)&bias[n];
            const float2 bf = __half22float2(bh);
            float2 v0, v1;
            v0.x = (float)acc[mt][nt][0] + bf.x;
            v0.y = (float)acc[mt][nt][1] + bf.y;
            v1.x = (float)acc[mt][nt][2] + bf.x;
            v1.y = (float)acc[mt][nt][3] + bf.y;
            *(float2*)&out[(size_t)m0 * N_DIM + n]       = v0;
            *(float2*)&out[(size_t)(m0 + 8) * N_DIM + n] = v1;
        }
    }
}

// ---------------------------------------------------------------------------
extern "C" void kernel_launch(void* const* d_in, const int* in_sizes, int n_in,
                              void* d_out, int out_size) {
    const void* x = nullptr;
    const void* w = nullptr;
    const void* b = nullptr;
    for (int i = 0; i < n_in; i++) {
        if (in_sizes[i] == M_DIM * K_DIM)      x = d_in[i];
        else if (in_sizes[i] == K_DIM * N_DIM) w = d_in[i];
        else                                   b = d_in[i];
    }
    float* out = (float*)d_out;

    static int smem_set = 0;
    if (!smem_set) {
        cudaFuncSetAttribute(tc_gemm_kernel,
                             cudaFuncAttributeMaxDynamicSharedMemorySize, SMEM_TOTAL);
        smem_set = 1;
    }

    probe_kernel<<<1, 1>>>();
    detect_kernel<<<1, 256>>>((const uint8_t*)x, (const uint8_t*)w);
    // tc path preprocessing
    pack_x_bf16_kernel<<<(M_DIM * (size_t)K_DIM) / (256 * 8), 256>>>(x);
    pack_w_bf16T_kernel<<<dim3(N_DIM / 32, K_DIM / 32), dim3(32, 8)>>>(w);
    // fallback preprocessing (no-ops when tc path live)
    pack_x_kernel<<<(M_DIM * (size_t)K_DIM) / (256 * 16), 256>>>((const int4*)x);
    transpose_w_kernel<<<dim3(N_DIM / 32, K_DIM / 32), dim3(32, 8)>>>(w);
    // GEMMs (exactly one does work)
    tc_gemm_kernel<<<dim3(N_DIM / TBN, M_DIM / TBM), 256, SMEM_TOTAL>>>(
        (const __half*)b, out);
    imma_gemm_kernel<<<dim3(N_DIM / FBN, M_DIM / FBM), 256>>>(
        (const __half*)b, out);
}

// round 11
// speedup vs baseline: 5.0351x; 1.1803x over previous
#include <cuda_runtime.h>
#include <cuda_fp16.h>
#include <cuda_bf16.h>
#include <cstdint>

#define M_DIM 16384
#define N_DIM 2048
#define K_DIM 2048

// ---- tcgen05 availability: only on arch-specific/family sm_100+ passes ----
#if defined(__CUDA_ARCH__) && (defined(__CUDA_ARCH_FEAT_SM103_ALL) ||          \
    defined(__CUDA_ARCH_FEAT_SM100_ALL) ||                                     \
    (defined(__CUDA_ARCH_FAMILY_SPECIFIC__) && (__CUDA_ARCH_FAMILY_SPECIFIC__ >= 1000)))
#define HAVE_TC 1
#else
#define HAVE_TC 0
#endif

// ---- allocation-free device scratch ---------------------------------------
__device__ __align__(256) __nv_bfloat16 g_xbf[(size_t)M_DIM * K_DIM];   // 64 MB
__device__ __align__(256) __nv_bfloat16 g_wTbf[(size_t)N_DIM * K_DIM]; //  8 MB [N][K]
__device__ int g_x_wide;
__device__ int g_w_wide;

// ---------------------------------------------------------------------------
// Detect int32-widened inputs (high byte of each 4B group is 0x00/0xFF).
// ---------------------------------------------------------------------------
__global__ void detect_kernel(const uint8_t* __restrict__ x,
                              const uint8_t* __restrict__ w) {
    __shared__ int sx, sw;
    if (threadIdx.x == 0) { sx = 1; sw = 1; }
    __syncthreads();
    int okx = 1, okw = 1;
    for (int i = threadIdx.x; i < 1024; i += 256) {
        uint8_t bx = x[4 * i + 3];
        uint8_t bw = w[4 * i + 3];
        if (bx != 0x00 && bx != 0xFF) okx = 0;
        if (bw != 0x00 && bw != 0xFF) okw = 0;
    }
    if (!okx) atomicAnd(&sx, 0);
    if (!okw) atomicAnd(&sw, 0);
    __syncthreads();
    if (threadIdx.x == 0) { g_x_wide = sx; g_w_wide = sw; }
}

// ---------------------------------------------------------------------------
// x -> bf16.  16 elements/thread.
// ---------------------------------------------------------------------------
__global__ void pack_x_bf16_kernel(const void* __restrict__ xin) {
    const size_t e0 = ((size_t)blockIdx.x * blockDim.x + threadIdx.x) * 16;
    if (e0 >= (size_t)M_DIM * K_DIM) return;
    __nv_bfloat16 tmp[16];
    if (g_x_wide) {
        const int4* p = (const int4*)xin + e0 / 4;
#pragma unroll
        for (int j = 0; j < 4; j++) {
            int4 v = p[j];
            tmp[4 * j + 0] = __int2bfloat16_rn(v.x);
            tmp[4 * j + 1] = __int2bfloat16_rn(v.y);
            tmp[4 * j + 2] = __int2bfloat16_rn(v.z);
            tmp[4 * j + 3] = __int2bfloat16_rn(v.w);
        }
    } else {
        const int8_t* p = (const int8_t*)xin + e0;
        int8_t b[16];
        *(int4*)b = *(const int4*)p;
#pragma unroll
        for (int j = 0; j < 16; j++) tmp[j] = __int2bfloat16_rn((int)b[j]);
    }
    *(uint4*)&g_xbf[e0]     = *(const uint4*)tmp;
    *(uint4*)&g_xbf[e0 + 8] = *(const uint4*)(tmp + 8);
}

// ---------------------------------------------------------------------------
// weight [K][N] -> g_wTbf [N][K] bf16.
// ---------------------------------------------------------------------------
__global__ void pack_w_bf16T_kernel(const void* __restrict__ w) {
    __shared__ __nv_bfloat16 tile[32][33];
    const int n0 = blockIdx.x * 32;
    const int k0 = blockIdx.y * 32;
    const int tx = threadIdx.x;
    const int ty = threadIdx.y;
    if (g_w_wide) {
        const int* w32 = (const int*)w;
#pragma unroll
        for (int j = 0; j < 32; j += 8)
            tile[ty + j][tx] = __int2bfloat16_rn(w32[(size_t)(k0 + ty + j) * N_DIM + (n0 + tx)]);
    } else {
        const int8_t* w8 = (const int8_t*)w;
#pragma unroll
        for (int j = 0; j < 32; j += 8)
            tile[ty + j][tx] = __int2bfloat16_rn((int)w8[(size_t)(k0 + ty + j) * N_DIM + (n0 + tx)]);
    }
    __syncthreads();
#pragma unroll
    for (int j = 0; j < 32; j += 8)
        g_wTbf[(size_t)(n0 + ty + j) * K_DIM + (k0 + tx)] = tile[tx][ty + j];
}

// ---------------------------------------------------------------------------
__device__ __forceinline__ uint32_t cvta_smem(const void* p) {
    return (uint32_t)__cvta_generic_to_shared(p);
}

// ===========================================================================
// tcgen05 bf16 GEMM.  CTA 256x256, K-chunk 64 elems (128B rows, SW128).
// 3 smem stages, 2 chunks of loads in flight, MMA waited one chunk late.
// Drain waits ONLY the final completion per barrier (parity-alias-safe).
// ===========================================================================
#define TBM 256
#define TBN 256
#define TBKE 64
#define KCHUNKS (K_DIM / TBKE)           // 32
#define NSTAGE 3

#define SWZ(o) ((o) ^ (((o) >> 3) & 0x70))

#define SM_TMEM 0
#define SM_MBAR 16
#define SM_A    1024                          // 3 stages x 32 KB
#define SM_B    (1024 + NSTAGE * 32768)       // 3 stages x 32 KB
#define SMEM_TOTAL (1024 + NSTAGE * 2 * 32768)   // 197632 B

#if HAVE_TC
__device__ __forceinline__ void mbar_init(uint32_t a, uint32_t cnt) {
    asm volatile("mbarrier.init.shared.b64 [%0], %1;" :: "r"(a), "r"(cnt) : "memory");
}
__device__ __forceinline__ void mbar_wait(uint32_t a, uint32_t parity) {
    asm volatile(
        "{\n\t"
        ".reg .pred P1;\n\t"
        "WAIT_LOOP_%=:\n\t"
        "mbarrier.try_wait.parity.shared.b64 P1, [%0], %1;\n\t"
        "@P1 bra.uni WAIT_DONE_%=;\n\t"
        "bra.uni WAIT_LOOP_%=;\n\t"
        "WAIT_DONE_%=:\n\t"
        "}"
        :: "r"(a), "r"(parity) : "memory");
}
static __device__ __forceinline__ uint64_t make_desc_sw128(uint32_t addr) {
    return ((uint64_t)2 << 61) | ((uint64_t)1 << 46) | ((uint64_t)64 << 32) |
           ((uint64_t)1 << 16) | (((uint64_t)addr >> 4) & 0x3FFF);
}
// idesc kind::f16 (bf16 in, fp32 acc): dtype F32@4, a/b BF16@[7]/[10],
// N/8@[17:22]=16 (N=128), M/16@[24:28]=8 (M=128)
#define IDESC_BF16 ((1u << 4) | (1u << 7) | (1u << 10) | (16u << 17) | (8u << 24))

__device__ __forceinline__ void mma_bf16_ss(uint32_t d_tmem, uint64_t a_desc,
                                            uint64_t b_desc, uint32_t en) {
    asm volatile(
        "{\n\t"
        ".reg .pred p;\n\t"
        "setp.ne.u32 p, %5, 0;\n\t"
        "tcgen05.mma.cta_group::1.kind::f16 [%0], %1, %2, %3, {%4,%4,%4,%4}, p;\n\t"
        "}"
        :: "r"(d_tmem), "l"(a_desc), "l"(b_desc), "r"(IDESC_BF16), "r"(0u), "r"(en)
        : "memory");
}
__device__ __forceinline__ void mma_commit(uint32_t mbar) {
    asm volatile(
        "tcgen05.commit.cta_group::1.mbarrier::arrive::one.shared::cluster.b64 [%0];"
        :: "r"(mbar) : "memory");
}
#endif  // HAVE_TC

__global__ __launch_bounds__(256, 1)
void tc_gemm_kernel(const __half* __restrict__ bias, float* __restrict__ out) {
#if HAVE_TC
    extern __shared__ __align__(1024) char smem[];
    const uint32_t smem_base = cvta_smem(smem);
    const int tid  = threadIdx.x;
    const int lane = tid & 31;
    const int wid  = tid >> 5;
    const int bn   = blockIdx.x;     // 0..7
    const int bm   = blockIdx.y;     // 0..63

    const __nv_bfloat16* gA = g_xbf  + (size_t)(bm * TBM) * K_DIM;
    const __nv_bfloat16* gB = g_wTbf + (size_t)(bn * TBN) * K_DIM;

    if (wid == 0) {
        asm volatile("tcgen05.alloc.cta_group::1.sync.aligned.shared::cta.b32 [%0], %1;"
                     :: "r"(smem_base + SM_TMEM), "r"(512u) : "memory");
        asm volatile("tcgen05.relinquish_alloc_permit.cta_group::1.sync.aligned;");
    }
    if (tid == 0) {
        mbar_init(smem_base + SM_MBAR, 1);
        mbar_init(smem_base + SM_MBAR + 8, 1);
    }
    __syncthreads();

    uint32_t tmem;
    asm volatile("ld.shared.b32 %0, [%1];" : "=r"(tmem) : "r"(smem_base + SM_TMEM));

    // ---- chunk loader: A 32 KB + B 32 KB into stage c%3, SW128 ------------
    auto load_chunk = [&](int c) {
        const int st = c % NSTAGE;
        const int kk = c * TBKE;
        const uint32_t abase = smem_base + SM_A + st * 32768;
        const uint32_t bbase = smem_base + SM_B + st * 32768;
#pragma unroll
        for (int i = 0; i < 8; i++) {
            const int idx = tid + i * 256;       // 0..2047
            const int row = idx >> 3;            // 0..255
            const int ce  = (idx & 7) * 8;       // element col
            const uint32_t dst = abase + SWZ(row * 128 + ce * 2);
            const __nv_bfloat16* src = gA + (size_t)row * K_DIM + kk + ce;
            asm volatile("cp.async.cg.shared.global [%0], [%1], 16;\n"
                         :: "r"(dst), "l"(src));
        }
#pragma unroll
        for (int i = 0; i < 8; i++) {
            const int idx = tid + i * 256;
            const int row = idx >> 3;
            const int ce  = (idx & 7) * 8;
            const uint32_t dst = bbase + SWZ(row * 128 + ce * 2);
            const __nv_bfloat16* src = gB + (size_t)row * K_DIM + kk + ce;
            asm volatile("cp.async.cg.shared.global [%0], [%1], 16;\n"
                         :: "r"(dst), "l"(src));
        }
        asm volatile("cp.async.commit_group;\n");
    };

    // 2 chunks in flight; stage(c+2) held chunk c-1 -> wait MMA(c-1) only.
    load_chunk(0);
    load_chunk(1);

    int ph[2] = {0, 0};
    auto wait_mma = [&](int c) {
        const int i = c & 1;
        mbar_wait(smem_base + SM_MBAR + i * 8, ph[i]);
        ph[i] ^= 1;
    };

    for (int c = 0; c < KCHUNKS; c++) {
        if (c < KCHUNKS - 1) asm volatile("cp.async.wait_group 1;\n");
        else                 asm volatile("cp.async.wait_group 0;\n");
        asm volatile("fence.proxy.async.shared::cta;" ::: "memory");
        __syncthreads();

        const int st = c % NSTAGE;
        if (tid == 0) {
            const uint64_t ad = make_desc_sw128(smem_base + SM_A + st * 32768);
            const uint64_t bd = make_desc_sw128(smem_base + SM_B + st * 32768);
#pragma unroll
            for (int k = 0; k < 4; k++) {        // k16 steps: +2 desc units
                const uint32_t en = (c > 0 || k > 0) ? 1u : 0u;
#pragma unroll
                for (int s = 0; s < 2; s++) {    // M slabs: +1024 units
                    const uint64_t a = ad + s * 1024 + k * 2;
                    mma_bf16_ss(tmem + s * 256,       a, bd + k * 2,        en);
                    mma_bf16_ss(tmem + s * 256 + 128, a, bd + 1024 + k * 2, en);
                }
            }
            mma_commit(smem_base + SM_MBAR + (c & 1) * 8);
        }

        if (c + 2 < KCHUNKS) {
            if (c >= 1) wait_mma(c - 1);         // lag<=1: alias-safe
            load_chunk(c + 2);
        }
    }

    // ---- drain: wait ONLY the final completion per barrier ----------------
    // bar0: 16 commits (even chunks), 15 in-loop waits -> ph[0]==1 == parity
    // of completion #16.  bar1: 16 commits (odd chunks), 14 in-loop waits ->
    // final completion #16 has parity 1 = ph[1]^1 (completion #15 is skipped;
    // in-order completion makes that safe, and waiting it would parity-alias).
    mbar_wait(smem_base + SM_MBAR,     ph[0]);       // == 1
    mbar_wait(smem_base + SM_MBAR + 8, ph[1] ^ 1);   // == 1
    asm volatile("tcgen05.fence::after_thread_sync;" ::: "memory");

    // ---- epilogue: warps 0-3 slab0 (TMEM cols 0..255), warps 4-7 slab1 ----
    const int slab = wid >> 2;
    const int sp   = wid & 3;
    const size_t m = (size_t)(bm * TBM + slab * 128 + sp * 32 + lane);
    const uint32_t dbase = tmem + slab * 256;

#pragma unroll
    for (int cb = 0; cb < 256; cb += 32) {
        uint32_t r[32];
        asm volatile(
            "tcgen05.ld.sync.aligned.32x32b.x32.b32 "
            "{%0,%1,%2,%3,%4,%5,%6,%7,%8,%9,%10,%11,%12,%13,%14,%15,"
            "%16,%17,%18,%19,%20,%21,%22,%23,%24,%25,%26,%27,%28,%29,%30,%31}, [%32];"
            : "=r"(r[0]), "=r"(r[1]), "=r"(r[2]), "=r"(r[3]),
              "=r"(r[4]), "=r"(r[5]), "=r"(r[6]), "=r"(r[7]),
              "=r"(r[8]), "=r"(r[9]), "=r"(r[10]), "=r"(r[11]),
              "=r"(r[12]), "=r"(r[13]), "=r"(r[14]), "=r"(r[15]),
              "=r"(r[16]), "=r"(r[17]), "=r"(r[18]), "=r"(r[19]),
              "=r"(r[20]), "=r"(r[21]), "=r"(r[22]), "=r"(r[23]),
              "=r"(r[24]), "=r"(r[25]), "=r"(r[26]), "=r"(r[27]),
              "=r"(r[28]), "=r"(r[29]), "=r"(r[30]), "=r"(r[31])
            : "r"(dbase + cb));
        asm volatile("tcgen05.wait::ld.sync.aligned;" ::: "memory");

        const int n0 = bn * TBN + cb;
        float* op = out + m * N_DIM + n0;
#pragma unroll
        for (int j = 0; j < 32; j += 4) {
            float4 v;
            v.x = __uint_as_float(r[j + 0]) + __half2float(bias[n0 + j + 0]);
            v.y = __uint_as_float(r[j + 1]) + __half2float(bias[n0 + j + 1]);
            v.z = __uint_as_float(r[j + 2]) + __half2float(bias[n0 + j + 2]);
            v.w = __uint_as_float(r[j + 3]) + __half2float(bias[n0 + j + 3]);
            *(float4*)&op[j] = v;
        }
    }

    __syncthreads();
    if (wid == 0) {
        asm volatile("tcgen05.dealloc.cta_group::1.sync.aligned.b32 %0, %1;"
                     :: "r"(tmem), "r"(512u));
    }
#endif  // HAVE_TC
}

// ---------------------------------------------------------------------------
extern "C" void kernel_launch(void* const* d_in, const int* in_sizes, int n_in,
                              void* d_out, int out_size) {
    const void* x = nullptr;
    const void* w = nullptr;
    const void* b = nullptr;
    for (int i = 0; i < n_in; i++) {
        if (in_sizes[i] == M_DIM * K_DIM)      x = d_in[i];
        else if (in_sizes[i] == K_DIM * N_DIM) w = d_in[i];
        else                                   b = d_in[i];
    }
    float* out = (float*)d_out;

    static int smem_set = 0;
    if (!smem_set) {
        cudaFuncSetAttribute(tc_gemm_kernel,
                             cudaFuncAttributeMaxDynamicSharedMemorySize, SMEM_TOTAL);
        smem_set = 1;
    }

    detect_kernel<<<1, 256>>>((const uint8_t*)x, (const uint8_t*)w);
    pack_x_bf16_kernel<<<(M_DIM * (size_t)K_DIM) / (256 * 16), 256>>>(x);
    pack_w_bf16T_kernel<<<dim3(N_DIM / 32, K_DIM / 32), dim3(32, 8)>>>(w);
    tc_gemm_kernel<<<dim3(N_DIM / TBN, M_DIM / TBM), 256, SMEM_TOTAL>>>(
        (const __half*)b, out);
}